// round 1
// baseline (speedup 1.0000x reference)
#include <cuda_runtime.h>
#include <cstdint>
#include <math.h>

// Problem constants (fixed by the dataset)
#define HDIM   1024
#define NAVAIL 32768
#define KFULL  2048          // 2*H part of K handled by GEMM0 (the +2 features go in epilogue)

// Tiling
#define BM 128
#define BN 128
#define BK 8
#define TM 8
#define TN 8
#define NTHREADS 256

// ---------------------------------------------------------------------------
// Scratch (no runtime allocation allowed -> device globals)
// ---------------------------------------------------------------------------
__device__ float g_h0[(size_t)NAVAIL * HDIM];   // 128 MiB
__device__ float g_h1[(size_t)NAVAIL * HDIM];   // 128 MiB
__device__ float g_scores[NAVAIL];

// ---------------------------------------------------------------------------
// GEMM layer 0: C[m,n] = lrelu( sum_k feat[m,k]*W0[k,n] + b0[n] )
// feat[m, 0:1024]    = x_m[m_ids[m], :]
// feat[m, 1024:2048] = x_op[op_idx[m], :]
// feat[m, 2048]      = job_srpt[job_ids[m]]   (epilogue rank-1 correction)
// feat[m, 2049]      = pt[m]                  (epilogue rank-1 correction)
// ---------------------------------------------------------------------------
__global__ __launch_bounds__(NTHREADS)
void gemm0_kernel(const float* __restrict__ x_m,
                  const float* __restrict__ x_op,
                  const float* __restrict__ job_srpt,
                  const float* __restrict__ pt,
                  const float* __restrict__ W0,
                  const float* __restrict__ b0,
                  const int*   __restrict__ m_ids,
                  const int*   __restrict__ op_idx,
                  const int*   __restrict__ job_ids,
                  float* __restrict__ out)
{
    __shared__ float As[2][BK][BM + 4];   // +4 pad: conflict-free transpose store, rows stay 16B aligned
    __shared__ float Bs[2][BK][BN];

    const int tid = threadIdx.x;
    const int bx  = blockIdx.x;   // N tile (0..7)
    const int by  = blockIdx.y;   // M tile (0..255)

    // A-tile loader mapping: one float4 per thread
    const int arow  = tid >> 1;          // 0..127
    const int akoff = (tid & 1) * 4;     // 0 or 4
    // B-tile loader mapping
    const int brow = tid >> 5;           // 0..7  (k within tile)
    const int bcol = (tid & 31) * 4;     // 0..124

    const int m_a = by * BM + arow;
    const float* pm = x_m  + (size_t)m_ids[m_a]  * HDIM;
    const float* po = x_op + (size_t)op_idx[m_a] * HDIM;

    float acc[TM][TN];
    #pragma unroll
    for (int i = 0; i < TM; ++i)
        #pragma unroll
        for (int j = 0; j < TN; ++j) acc[i][j] = 0.f;

    // --- load tile 0 directly into smem ---
    {
        const int k = akoff;
        const float* src = (k < HDIM) ? (pm + k) : (po + (k - HDIM));
        float4 a = *(const float4*)src;
        As[0][akoff + 0][arow] = a.x;
        As[0][akoff + 1][arow] = a.y;
        As[0][akoff + 2][arow] = a.z;
        As[0][akoff + 3][arow] = a.w;
        float4 b = *(const float4*)(W0 + (size_t)brow * HDIM + bx * BN + bcol);
        *(float4*)&Bs[0][brow][bcol] = b;
    }
    __syncthreads();

    const int nT = KFULL / BK;   // 256
    const int ty = tid >> 4, tx = tid & 15;
    float4 aReg, bReg;

    for (int kt = 0; kt < nT; ++kt) {
        const int cur = kt & 1;
        if (kt + 1 < nT) {
            const int k = (kt + 1) * BK + akoff;
            const float* src = (k < HDIM) ? (pm + k) : (po + (k - HDIM));
            aReg = *(const float4*)src;
            bReg = *(const float4*)(W0 + (size_t)((kt + 1) * BK + brow) * HDIM + bx * BN + bcol);
        }
        #pragma unroll
        for (int kk = 0; kk < BK; ++kk) {
            float a[TM], b[TN];
            *(float4*)&a[0] = *(const float4*)&As[cur][kk][ty * TM];
            *(float4*)&a[4] = *(const float4*)&As[cur][kk][ty * TM + 4];
            *(float4*)&b[0] = *(const float4*)&Bs[cur][kk][tx * TN];
            *(float4*)&b[4] = *(const float4*)&Bs[cur][kk][tx * TN + 4];
            #pragma unroll
            for (int i = 0; i < TM; ++i)
                #pragma unroll
                for (int j = 0; j < TN; ++j)
                    acc[i][j] = fmaf(a[i], b[j], acc[i][j]);
        }
        if (kt + 1 < nT) {
            const int nb = cur ^ 1;
            As[nb][akoff + 0][arow] = aReg.x;
            As[nb][akoff + 1][arow] = aReg.y;
            As[nb][akoff + 2][arow] = aReg.z;
            As[nb][akoff + 3][arow] = aReg.w;
            *(float4*)&Bs[nb][brow][bcol] = bReg;
            __syncthreads();
        }
    }

    // --- epilogue: bias + rank-2 scalar-feature correction + leaky relu ---
    const int m0 = by * BM + ty * TM;
    const int n0 = bx * BN + tx * TN;
    float bias[TN], w1[TN], w2[TN];
    *(float4*)&bias[0] = *(const float4*)(b0 + n0);
    *(float4*)&bias[4] = *(const float4*)(b0 + n0 + 4);
    *(float4*)&w1[0]   = *(const float4*)(W0 + (size_t)2048 * HDIM + n0);
    *(float4*)&w1[4]   = *(const float4*)(W0 + (size_t)2048 * HDIM + n0 + 4);
    *(float4*)&w2[0]   = *(const float4*)(W0 + (size_t)2049 * HDIM + n0);
    *(float4*)&w2[4]   = *(const float4*)(W0 + (size_t)2049 * HDIM + n0 + 4);

    #pragma unroll
    for (int i = 0; i < TM; ++i) {
        const int m = m0 + i;
        const float js = job_srpt[job_ids[m]];
        const float pv = pt[m];
        float v[TN];
        #pragma unroll
        for (int j = 0; j < TN; ++j) {
            float t = acc[i][j] + bias[j] + js * w1[j] + pv * w2[j];
            v[j] = t > 0.f ? t : 0.01f * t;
        }
        *(float4*)(out + (size_t)m * HDIM + n0)     = make_float4(v[0], v[1], v[2], v[3]);
        *(float4*)(out + (size_t)m * HDIM + n0 + 4) = make_float4(v[4], v[5], v[6], v[7]);
    }
}

// ---------------------------------------------------------------------------
// GEMM layers 1/2: C = lrelu(A @ W + b),  A:[N,1024], W:[1024,1024]
// ---------------------------------------------------------------------------
__global__ __launch_bounds__(NTHREADS)
void gemm_h_kernel(const float* __restrict__ A,
                   const float* __restrict__ W,
                   const float* __restrict__ bias_in,
                   float* __restrict__ out)
{
    __shared__ float As[2][BK][BM + 4];
    __shared__ float Bs[2][BK][BN];

    const int tid = threadIdx.x;
    const int bx  = blockIdx.x;
    const int by  = blockIdx.y;

    const int arow  = tid >> 1;
    const int akoff = (tid & 1) * 4;
    const int brow  = tid >> 5;
    const int bcol  = (tid & 31) * 4;

    const float* arp = A + (size_t)(by * BM + arow) * HDIM;

    float acc[TM][TN];
    #pragma unroll
    for (int i = 0; i < TM; ++i)
        #pragma unroll
        for (int j = 0; j < TN; ++j) acc[i][j] = 0.f;

    {
        float4 a = *(const float4*)(arp + akoff);
        As[0][akoff + 0][arow] = a.x;
        As[0][akoff + 1][arow] = a.y;
        As[0][akoff + 2][arow] = a.z;
        As[0][akoff + 3][arow] = a.w;
        float4 b = *(const float4*)(W + (size_t)brow * HDIM + bx * BN + bcol);
        *(float4*)&Bs[0][brow][bcol] = b;
    }
    __syncthreads();

    const int nT = HDIM / BK;   // 128
    const int ty = tid >> 4, tx = tid & 15;
    float4 aReg, bReg;

    for (int kt = 0; kt < nT; ++kt) {
        const int cur = kt & 1;
        if (kt + 1 < nT) {
            aReg = *(const float4*)(arp + (kt + 1) * BK + akoff);
            bReg = *(const float4*)(W + (size_t)((kt + 1) * BK + brow) * HDIM + bx * BN + bcol);
        }
        #pragma unroll
        for (int kk = 0; kk < BK; ++kk) {
            float a[TM], b[TN];
            *(float4*)&a[0] = *(const float4*)&As[cur][kk][ty * TM];
            *(float4*)&a[4] = *(const float4*)&As[cur][kk][ty * TM + 4];
            *(float4*)&b[0] = *(const float4*)&Bs[cur][kk][tx * TN];
            *(float4*)&b[4] = *(const float4*)&Bs[cur][kk][tx * TN + 4];
            #pragma unroll
            for (int i = 0; i < TM; ++i)
                #pragma unroll
                for (int j = 0; j < TN; ++j)
                    acc[i][j] = fmaf(a[i], b[j], acc[i][j]);
        }
        if (kt + 1 < nT) {
            const int nb = cur ^ 1;
            As[nb][akoff + 0][arow] = aReg.x;
            As[nb][akoff + 1][arow] = aReg.y;
            As[nb][akoff + 2][arow] = aReg.z;
            As[nb][akoff + 3][arow] = aReg.w;
            *(float4*)&Bs[nb][brow][bcol] = bReg;
            __syncthreads();
        }
    }

    const int m0 = by * BM + ty * TM;
    const int n0 = bx * BN + tx * TN;
    float bias[TN];
    *(float4*)&bias[0] = *(const float4*)(bias_in + n0);
    *(float4*)&bias[4] = *(const float4*)(bias_in + n0 + 4);

    #pragma unroll
    for (int i = 0; i < TM; ++i) {
        const int m = m0 + i;
        float v[TN];
        #pragma unroll
        for (int j = 0; j < TN; ++j) {
            float t = acc[i][j] + bias[j];
            v[j] = t > 0.f ? t : 0.01f * t;
        }
        *(float4*)(out + (size_t)m * HDIM + n0)     = make_float4(v[0], v[1], v[2], v[3]);
        *(float4*)(out + (size_t)m * HDIM + n0 + 4) = make_float4(v[4], v[5], v[6], v[7]);
    }
}

// ---------------------------------------------------------------------------
// Final layer: scores[m] = h2[m,:] . W3 + b3    (one warp per row)
// ---------------------------------------------------------------------------
__global__ void gemv_kernel(const float* __restrict__ hbuf,
                            const float* __restrict__ W3,
                            const float* __restrict__ b3,
                            float* __restrict__ scores)
{
    const int gw   = (int)((blockIdx.x * blockDim.x + threadIdx.x) >> 5);
    const int lane = threadIdx.x & 31;
    if (gw >= NAVAIL) return;
    const float4* hr = (const float4*)(hbuf + (size_t)gw * HDIM);
    const float4* wr = (const float4*)W3;
    float s = 0.f;
    #pragma unroll 4
    for (int i = lane; i < HDIM / 4; i += 32) {
        float4 a = hr[i];
        float4 w = wr[i];
        s += a.x * w.x + a.y * w.y + a.z * w.z + a.w * w.w;
    }
    #pragma unroll
    for (int off = 16; off > 0; off >>= 1)
        s += __shfl_down_sync(0xffffffffu, s, off);
    if (lane == 0) scores[gw] = s + b3[0];
}

// ---------------------------------------------------------------------------
// Softmax over 32768 scores + argmax (first-max semantics), single block.
// out[0:N) = probs; out[N:out_size) = (float)argmax_idx
// ---------------------------------------------------------------------------
__global__ void softmax_kernel(const float* __restrict__ scores,
                               float* __restrict__ out, int out_size)
{
    const int tid  = threadIdx.x;      // 1024 threads = 32 warps
    const int lane = tid & 31;
    const int wid  = tid >> 5;
    __shared__ float red_f[32];
    __shared__ int   red_i[32];
    __shared__ float red_s[32];

    // pass 1: max + first-argmax
    float bmax = -INFINITY;
    int   bidx = 0x7fffffff;
    for (int i = tid; i < NAVAIL; i += 1024) {
        float v = scores[i];
        if (v > bmax) { bmax = v; bidx = i; }   // i strictly increasing per thread
    }
    #pragma unroll
    for (int off = 16; off > 0; off >>= 1) {
        float om = __shfl_down_sync(0xffffffffu, bmax, off);
        int   oi = __shfl_down_sync(0xffffffffu, bidx, off);
        if (om > bmax || (om == bmax && oi < bidx)) { bmax = om; bidx = oi; }
    }
    if (lane == 0) { red_f[wid] = bmax; red_i[wid] = bidx; }
    __syncthreads();
    if (tid < 32) {
        bmax = red_f[tid];
        bidx = red_i[tid];
        #pragma unroll
        for (int off = 16; off > 0; off >>= 1) {
            float om = __shfl_down_sync(0xffffffffu, bmax, off);
            int   oi = __shfl_down_sync(0xffffffffu, bidx, off);
            if (om > bmax || (om == bmax && oi < bidx)) { bmax = om; bidx = oi; }
        }
        if (tid == 0) { red_f[0] = bmax; red_i[0] = bidx; }
    }
    __syncthreads();
    const float gmax = red_f[0];
    const int   gidx = red_i[0];

    // pass 2: exp + sum (store raw exp into out, rescale after)
    float s = 0.f;
    for (int i = tid; i < NAVAIL; i += 1024) {
        float e = expf(scores[i] - gmax);
        out[i] = e;
        s += e;
    }
    #pragma unroll
    for (int off = 16; off > 0; off >>= 1)
        s += __shfl_down_sync(0xffffffffu, s, off);
    if (lane == 0) red_s[wid] = s;
    __syncthreads();
    if (tid < 32) {
        s = red_s[tid];
        #pragma unroll
        for (int off = 16; off > 0; off >>= 1)
            s += __shfl_down_sync(0xffffffffu, s, off);
        if (tid == 0) red_s[0] = s;
    }
    __syncthreads();
    const float inv = 1.0f / red_s[0];
    for (int i = tid; i < NAVAIL; i += 1024)
        out[i] *= inv;
    // trailing output element(s): the greedy action index
    for (int i = NAVAIL + tid; i < out_size; i += 1024)
        out[i] = (float)gidx;
}

// ---------------------------------------------------------------------------
// Launch
// inputs (metadata order): x_m, x_op, job_srpt, pt, W0, b0, W1, b1, W2, b2,
//                          W3, b3, m_ids, op_idx, job_ids
// ---------------------------------------------------------------------------
extern "C" void kernel_launch(void* const* d_in, const int* in_sizes, int n_in,
                              void* d_out, int out_size)
{
    const float* x_m      = (const float*)d_in[0];
    const float* x_op     = (const float*)d_in[1];
    const float* job_srpt = (const float*)d_in[2];
    const float* pt       = (const float*)d_in[3];
    const float* W0       = (const float*)d_in[4];
    const float* b0       = (const float*)d_in[5];
    const float* W1       = (const float*)d_in[6];
    const float* b1       = (const float*)d_in[7];
    const float* W2       = (const float*)d_in[8];
    const float* b2       = (const float*)d_in[9];
    const float* W3       = (const float*)d_in[10];
    const float* b3       = (const float*)d_in[11];
    const int*   m_ids    = (const int*)d_in[12];
    const int*   op_idx   = (const int*)d_in[13];
    const int*   job_ids  = (const int*)d_in[14];
    float* out = (float*)d_out;

    float *h0, *h1, *sc;
    cudaGetSymbolAddress((void**)&h0, g_h0);
    cudaGetSymbolAddress((void**)&h1, g_h1);
    cudaGetSymbolAddress((void**)&sc, g_scores);

    const dim3 grid(HDIM / BN, NAVAIL / BM);   // (8, 256)

    gemm0_kernel<<<grid, NTHREADS>>>(x_m, x_op, job_srpt, pt, W0, b0,
                                     m_ids, op_idx, job_ids, h0);
    gemm_h_kernel<<<grid, NTHREADS>>>(h0, W1, b1, h1);
    gemm_h_kernel<<<grid, NTHREADS>>>(h1, W2, b2, h0);
    gemv_kernel<<<NAVAIL / 8, 256>>>(h0, W3, b3, sc);
    softmax_kernel<<<1, 1024>>>(sc, out, out_size);
}

// round 5
// speedup vs baseline: 2.0905x; 2.0905x over previous
#include <cuda_runtime.h>
#include <cuda_bf16.h>
#include <cstdint>
#include <math.h>

// ---------------------------------------------------------------------------
// Problem constants
// ---------------------------------------------------------------------------
#define HDIM   1024
#define NAVAIL 32768
#define KFULL  2048      // GEMM0 K (the +2 scalar features handled in epilogue)

// GEMM tiling (mma.sync m16n8k16 bf16)
#define BM 128
#define BN 128
#define BK 16
#define NTHREADS 256     // 8 warps: 4 (M) x 2 (N)

// Padded smem row stride: 16 bf16 = 32B, padded to 48B.
// 48 mod 128 over 8 rows walks {0,48,96,16,64,112,32,80} -> conflict-free ldmatrix.
#define SROWB 48
#define TILE_BYTES (128 * SROWB)          // 6144 per bf16 tile
#define STG_AH 0
#define STG_AL (TILE_BYTES)
#define STG_BH (2 * TILE_BYTES)
#define STG_BL (3 * TILE_BYTES)
#define STG_STRIDE (4 * TILE_BYTES)       // 24576 per stage
#define SMEM_BYTES (2 * STG_STRIDE)       // 49152 == default cap, no opt-in needed

// ---------------------------------------------------------------------------
// Device scratch (no runtime allocation allowed)
// ---------------------------------------------------------------------------
__device__ float g_h0[(size_t)NAVAIL * HDIM];   // 128 MiB
__device__ float g_h1[(size_t)NAVAIL * HDIM];   // 128 MiB
__device__ float g_scores[NAVAIL];
__device__ __nv_bfloat16 g_wt0h[(size_t)HDIM * KFULL];  // W0^T hi [1024 x 2048]
__device__ __nv_bfloat16 g_wt0l[(size_t)HDIM * KFULL];
__device__ __nv_bfloat16 g_wt1h[(size_t)HDIM * HDIM];
__device__ __nv_bfloat16 g_wt1l[(size_t)HDIM * HDIM];
__device__ __nv_bfloat16 g_wt2h[(size_t)HDIM * HDIM];
__device__ __nv_bfloat16 g_wt2l[(size_t)HDIM * HDIM];

// ---------------------------------------------------------------------------
// Helpers (all sm_80-era PTX; nothing arch-accelerated)
// ---------------------------------------------------------------------------
__device__ __forceinline__ uint32_t smem_u32(const void* p) {
    uint32_t a;
    asm("{ .reg .u64 t; cvta.to.shared.u64 t, %1; cvt.u32.u64 %0, t; }"
        : "=r"(a) : "l"(p));
    return a;
}
__device__ __forceinline__ void ldmx4(uint32_t* r, uint32_t addr) {
    asm volatile("ldmatrix.sync.aligned.m8n8.x4.shared.b16 {%0,%1,%2,%3}, [%4];"
                 : "=r"(r[0]), "=r"(r[1]), "=r"(r[2]), "=r"(r[3]) : "r"(addr));
}
__device__ __forceinline__ void mma_bf16(float* d, const uint32_t* a,
                                         uint32_t b0, uint32_t b1) {
    asm volatile("mma.sync.aligned.m16n8k16.row.col.f32.bf16.bf16.f32 "
                 "{%0,%1,%2,%3}, {%4,%5,%6,%7}, {%8,%9}, {%0,%1,%2,%3};"
                 : "+f"(d[0]), "+f"(d[1]), "+f"(d[2]), "+f"(d[3])
                 : "r"(a[0]), "r"(a[1]), "r"(a[2]), "r"(a[3]), "r"(b0), "r"(b1));
}
__device__ __forceinline__ void cp16(uint32_t dst, const void* src) {
    asm volatile("cp.async.cg.shared.global [%0], [%1], 16;"
                 :: "r"(dst), "l"(src) : "memory");
}
#define CP_COMMIT() asm volatile("cp.async.commit_group;" ::: "memory")
#define CP_WAIT0()  asm volatile("cp.async.wait_group 0;" ::: "memory")

__device__ __forceinline__ void split2(float a, float b, uint32_t& hi, uint32_t& lo) {
    __nv_bfloat16 ha = __float2bfloat16_rn(a);
    __nv_bfloat16 hb = __float2bfloat16_rn(b);
    __nv_bfloat16 la = __float2bfloat16_rn(a - __bfloat162float(ha));
    __nv_bfloat16 lb = __float2bfloat16_rn(b - __bfloat162float(hb));
    __nv_bfloat162 H; H.x = ha; H.y = hb;
    __nv_bfloat162 L; L.x = la; L.y = lb;
    hi = *reinterpret_cast<uint32_t*>(&H);
    lo = *reinterpret_cast<uint32_t*>(&L);
}

// ---------------------------------------------------------------------------
// Prep: transpose + bf16 hi/lo split of a [K x N] fp32 weight into [N x K]
// ---------------------------------------------------------------------------
__global__ void transpose_split_kernel(const float* __restrict__ W, int K, int N,
                                       __nv_bfloat16* __restrict__ Th,
                                       __nv_bfloat16* __restrict__ Tl) {
    __shared__ float t[32][33];
    const int nb = blockIdx.x * 32, kb = blockIdx.y * 32;
    const int tx = threadIdx.x, ty = threadIdx.y;   // (32, 8)
    #pragma unroll
    for (int j = 0; j < 32; j += 8)
        t[ty + j][tx] = W[(size_t)(kb + ty + j) * N + nb + tx];
    __syncthreads();
    #pragma unroll
    for (int j = 0; j < 32; j += 8) {
        const float x = t[tx][ty + j];
        const __nv_bfloat16 h = __float2bfloat16_rn(x);
        const __nv_bfloat16 l = __float2bfloat16_rn(x - __bfloat162float(h));
        const size_t o = (size_t)(nb + ty + j) * K + kb + tx;
        Th[o] = h;
        Tl[o] = l;
    }
}

// ---------------------------------------------------------------------------
// Split-bf16 GEMM layer on mma.sync:
//   out[M,1024] = lrelu( A[M,K] @ W[K,1024] + bias (+ L0 scalar features) )
//   A fp32 (hi/lo split inline; L0 gather via per-thread register pointers),
//   W pre-split bf16 [N,K] in global.
//   Split product: A*B ~= Ah*Bh + Ah*Bl + Al*Bh  (lo*lo dropped, ~1e-5 rel)
// ---------------------------------------------------------------------------
template <int KTOT, bool L0>
__global__ __launch_bounds__(NTHREADS)
void gemm_mma_kernel(const float* __restrict__ A,          // L0: x_m
                     const float* __restrict__ x_op,
                     const __nv_bfloat16* __restrict__ WTh,
                     const __nv_bfloat16* __restrict__ WTl,
                     const float* __restrict__ bias,
                     const float* __restrict__ W0tail,     // rows 2048/2049 of W0
                     const float* __restrict__ job_srpt,
                     const float* __restrict__ pt,
                     const int* __restrict__ m_ids,
                     const int* __restrict__ op_idx,
                     const int* __restrict__ job_ids,
                     float* __restrict__ out) {
    extern __shared__ char sm[];
    const uint32_t sbase = smem_u32(sm);

    const int tid  = threadIdx.x;
    const int wid  = tid >> 5;
    const int lane = tid & 31;
    const int wm   = wid >> 1;       // 0..3 (M)
    const int wn   = wid & 1;        // 0..1 (N)
    const int n0   = blockIdx.x * BN;
    const int m0   = blockIdx.y * BM;

    // A-load mapping: tile is 128 rows x 16 fp32 = 512 float4; 2 per thread.
    // rows: r0 = tid>>2, r1 = r0 + 64; c4 = tid&3.
    const int r0 = tid >> 2;
    const int r1 = r0 + 64;
    const int c4 = tid & 3;
    const float *pa0, *pb0, *pa1, *pb1;   // per-row source pointers (regs)
    if (L0) {
        pa0 = A + (size_t)m_ids[m0 + r0] * HDIM;
        pb0 = x_op + (size_t)op_idx[m0 + r0] * HDIM;
        pa1 = A + (size_t)m_ids[m0 + r1] * HDIM;
        pb1 = x_op + (size_t)op_idx[m0 + r1] * HDIM;
    } else {
        pa0 = A + (size_t)(m0 + r0) * HDIM;
        pa1 = A + (size_t)(m0 + r1) * HDIM;
        pb0 = pb1 = nullptr;
    }

    float acc[2][8][4];
    #pragma unroll
    for (int i = 0; i < 2; ++i)
        #pragma unroll
        for (int j = 0; j < 8; ++j)
            #pragma unroll
            for (int r = 0; r < 4; ++r) acc[i][j][r] = 0.f;

    const int T = KTOT / BK;

    auto ldgA = [&](int t, float4* aR) {
        const int kbase = t * BK;
        const float* s0;
        const float* s1;
        if (L0) {
            const bool first = (kbase < HDIM);
            s0 = first ? (pa0 + kbase) : (pb0 + (kbase - HDIM));
            s1 = first ? (pa1 + kbase) : (pb1 + (kbase - HDIM));
        } else {
            s0 = pa0 + kbase;
            s1 = pa1 + kbase;
        }
        aR[0] = *(const float4*)(s0 + c4 * 4);
        aR[1] = *(const float4*)(s1 + c4 * 4);
    };
    auto stsA = [&](int buf, const float4* aR) {
        char* bb = sm + (size_t)buf * STG_STRIDE;
        #pragma unroll
        for (int i = 0; i < 2; ++i) {
            const int row = i ? r1 : r0;
            uint32_t h01, l01, h23, l23;
            split2(aR[i].x, aR[i].y, h01, l01);
            split2(aR[i].z, aR[i].w, h23, l23);
            const uint32_t off = row * SROWB + c4 * 8;
            *(uint2*)(bb + STG_AH + off) = make_uint2(h01, h23);
            *(uint2*)(bb + STG_AL + off) = make_uint2(l01, l23);
        }
    };
    auto cpB = [&](int t, int buf) {
        const int kbase = t * BK;
        const uint32_t st = sbase + buf * STG_STRIDE;
        #pragma unroll
        for (int i = 0; i < 2; ++i) {
            const int idx = tid + i * 256;       // 0..511
            const int mat = idx >> 8;            // 0=hi, 1=lo
            const int rem = idx & 255;
            const int row = rem >> 1;            // 0..127 (N)
            const int ch  = rem & 1;             // 16B chunk (8 bf16)
            const __nv_bfloat16* src =
                (mat ? WTl : WTh) + (size_t)(n0 + row) * KTOT + kbase + ch * 8;
            const uint32_t dst = st + (mat ? STG_BL : STG_BH) + row * SROWB + ch * 16;
            cp16(dst, src);
        }
        CP_COMMIT();
    };

    // ---- prologue: stage 0 ----
    {
        float4 aR[2];
        ldgA(0, aR);
        cpB(0, 0);
        stsA(0, aR);
        CP_WAIT0();
        __syncthreads();
    }

    const uint32_t lrow = (lane & 15);
    const uint32_t kcol2 = (lane >> 4) * 16;     // byte offset of k-half (8 bf16)

    for (int t = 0; t < T; ++t) {
        const int cur = t & 1;
        float4 aR[2];
        if (t + 1 < T) {
            cpB(t + 1, cur ^ 1);       // buffer cur^1 free: all reads of it fenced
            ldgA(t + 1, aR);           //   by the barrier at the end of iter t-1
        }

        const uint32_t st = sbase + cur * STG_STRIDE;
        uint32_t ah[2][4], al[2][4], bh[4][4], bl[4][4];
        #pragma unroll
        for (int mt = 0; mt < 2; ++mt) {
            const uint32_t ra = (wm * 32 + mt * 16 + lrow) * SROWB + kcol2;
            ldmx4(ah[mt], st + STG_AH + ra);
            ldmx4(al[mt], st + STG_AL + ra);
        }
        #pragma unroll
        for (int p = 0; p < 4; ++p) {
            const uint32_t rb = (wn * 64 + p * 16 + lrow) * SROWB + kcol2;
            ldmx4(bh[p], st + STG_BH + rb);
            ldmx4(bl[p], st + STG_BL + rb);
        }
        #pragma unroll
        for (int mt = 0; mt < 2; ++mt)
            #pragma unroll
            for (int nt = 0; nt < 8; ++nt) {
                const int p = nt >> 1, o = nt & 1;
                mma_bf16(acc[mt][nt], ah[mt], bh[p][o], bh[p][2 + o]);
                mma_bf16(acc[mt][nt], ah[mt], bl[p][o], bl[p][2 + o]);
                mma_bf16(acc[mt][nt], al[mt], bh[p][o], bh[p][2 + o]);
            }

        if (t + 1 < T) {
            __syncthreads();           // all warps done reading buffer cur^1 (iter t-1)
            stsA(cur ^ 1, aR);         //   ...and done with A region before overwrite
            CP_WAIT0();
            __syncthreads();
        }
    }

    // ---- epilogue: fragments -> bias (+L0 features) -> lrelu -> global ----
    const int gq = lane >> 2;         // 0..7 row-in-8-group
    const int tg = lane & 3;          // col pair selector
    #pragma unroll
    for (int mt = 0; mt < 2; ++mt) {
        const int er0 = m0 + wm * 32 + mt * 16 + gq;
        const int er1 = er0 + 8;
        float js0 = 0.f, pv0 = 0.f, js1 = 0.f, pv1 = 0.f;
        if (L0) {
            js0 = job_srpt[job_ids[er0]]; pv0 = pt[er0];
            js1 = job_srpt[job_ids[er1]]; pv1 = pt[er1];
        }
        #pragma unroll
        for (int nt = 0; nt < 8; ++nt) {
            const int nc = n0 + wn * 64 + nt * 8 + tg * 2;
            const float bz0 = bias[nc], bz1 = bias[nc + 1];
            float e00 = 0.f, e01 = 0.f, e10 = 0.f, e11 = 0.f;
            if (L0) {
                const float wa0 = W0tail[nc], wa1 = W0tail[nc + 1];
                const float wb0 = W0tail[HDIM + nc], wb1 = W0tail[HDIM + nc + 1];
                e00 = js0 * wa0 + pv0 * wb0; e01 = js0 * wa1 + pv0 * wb1;
                e10 = js1 * wa0 + pv1 * wb0; e11 = js1 * wa1 + pv1 * wb1;
            }
            float v00 = acc[mt][nt][0] + bz0 + e00;
            float v01 = acc[mt][nt][1] + bz1 + e01;
            float v10 = acc[mt][nt][2] + bz0 + e10;
            float v11 = acc[mt][nt][3] + bz1 + e11;
            v00 = v00 > 0.f ? v00 : 0.01f * v00;
            v01 = v01 > 0.f ? v01 : 0.01f * v01;
            v10 = v10 > 0.f ? v10 : 0.01f * v10;
            v11 = v11 > 0.f ? v11 : 0.01f * v11;
            *(float2*)(out + (size_t)er0 * HDIM + nc) = make_float2(v00, v01);
            *(float2*)(out + (size_t)er1 * HDIM + nc) = make_float2(v10, v11);
        }
    }
}

// ---------------------------------------------------------------------------
// Final layer GEMV: scores[m] = h[m,:] . W3 + b3
// ---------------------------------------------------------------------------
__global__ void gemv_kernel(const float* __restrict__ hbuf,
                            const float* __restrict__ W3,
                            const float* __restrict__ b3,
                            float* __restrict__ scores) {
    const int gw = (int)((blockIdx.x * blockDim.x + threadIdx.x) >> 5);
    const int lane = threadIdx.x & 31;
    if (gw >= NAVAIL) return;
    const float4* hr = (const float4*)(hbuf + (size_t)gw * HDIM);
    const float4* wr = (const float4*)W3;
    float s = 0.f;
    #pragma unroll 4
    for (int i = lane; i < HDIM / 4; i += 32) {
        const float4 a = hr[i];
        const float4 w = wr[i];
        s += a.x * w.x + a.y * w.y + a.z * w.z + a.w * w.w;
    }
    #pragma unroll
    for (int off = 16; off > 0; off >>= 1)
        s += __shfl_down_sync(0xffffffffu, s, off);
    if (lane == 0) scores[gw] = s + b3[0];
}

// ---------------------------------------------------------------------------
// Softmax + argmax (first-max semantics), single block.
// ---------------------------------------------------------------------------
__global__ void softmax_kernel(const float* __restrict__ scores,
                               float* __restrict__ out, int out_size) {
    const int tid = threadIdx.x;
    const int lane = tid & 31;
    const int wid = tid >> 5;
    __shared__ float red_f[32];
    __shared__ int   red_i[32];
    __shared__ float red_s[32];

    float bmax = -INFINITY;
    int bidx = 0x7fffffff;
    for (int i = tid; i < NAVAIL; i += 1024) {
        const float v = scores[i];
        if (v > bmax) { bmax = v; bidx = i; }
    }
    #pragma unroll
    for (int off = 16; off > 0; off >>= 1) {
        const float om = __shfl_down_sync(0xffffffffu, bmax, off);
        const int oi = __shfl_down_sync(0xffffffffu, bidx, off);
        if (om > bmax || (om == bmax && oi < bidx)) { bmax = om; bidx = oi; }
    }
    if (lane == 0) { red_f[wid] = bmax; red_i[wid] = bidx; }
    __syncthreads();
    if (tid < 32) {
        bmax = red_f[tid];
        bidx = red_i[tid];
        #pragma unroll
        for (int off = 16; off > 0; off >>= 1) {
            const float om = __shfl_down_sync(0xffffffffu, bmax, off);
            const int oi = __shfl_down_sync(0xffffffffu, bidx, off);
            if (om > bmax || (om == bmax && oi < bidx)) { bmax = om; bidx = oi; }
        }
        if (tid == 0) { red_f[0] = bmax; red_i[0] = bidx; }
    }
    __syncthreads();
    const float gmax = red_f[0];
    const int gidx = red_i[0];

    float s = 0.f;
    for (int i = tid; i < NAVAIL; i += 1024) {
        const float e = expf(scores[i] - gmax);
        out[i] = e;
        s += e;
    }
    #pragma unroll
    for (int off = 16; off > 0; off >>= 1)
        s += __shfl_down_sync(0xffffffffu, s, off);
    if (lane == 0) red_s[wid] = s;
    __syncthreads();
    if (tid < 32) {
        s = red_s[tid];
        #pragma unroll
        for (int off = 16; off > 0; off >>= 1)
            s += __shfl_down_sync(0xffffffffu, s, off);
        if (tid == 0) red_s[0] = s;
    }
    __syncthreads();
    const float inv = 1.0f / red_s[0];
    for (int i = tid; i < NAVAIL; i += 1024)
        out[i] *= inv;
    for (int i = NAVAIL + tid; i < out_size; i += 1024)
        out[i] = (float)gidx;
}

// ---------------------------------------------------------------------------
// Launch. inputs: x_m, x_op, job_srpt, pt, W0, b0, W1, b1, W2, b2, W3, b3,
//                 m_ids, op_idx, job_ids
// Host API surface kept to the R1-proven minimum:
//   cudaGetSymbolAddress + kernel launches only (no cudaFuncSetAttribute).
// ---------------------------------------------------------------------------
extern "C" void kernel_launch(void* const* d_in, const int* in_sizes, int n_in,
                              void* d_out, int out_size) {
    const float* x_m      = (const float*)d_in[0];
    const float* x_op     = (const float*)d_in[1];
    const float* job_srpt = (const float*)d_in[2];
    const float* pt       = (const float*)d_in[3];
    const float* W0       = (const float*)d_in[4];
    const float* b0       = (const float*)d_in[5];
    const float* W1       = (const float*)d_in[6];
    const float* b1       = (const float*)d_in[7];
    const float* W2       = (const float*)d_in[8];
    const float* b2       = (const float*)d_in[9];
    const float* W3       = (const float*)d_in[10];
    const float* b3       = (const float*)d_in[11];
    const int*   m_ids    = (const int*)d_in[12];
    const int*   op_idx   = (const int*)d_in[13];
    const int*   job_ids  = (const int*)d_in[14];
    float* out = (float*)d_out;

    float *h0, *h1, *sc;
    __nv_bfloat16 *w0h, *w0l, *w1h, *w1l, *w2h, *w2l;
    cudaGetSymbolAddress((void**)&h0, g_h0);
    cudaGetSymbolAddress((void**)&h1, g_h1);
    cudaGetSymbolAddress((void**)&sc, g_scores);
    cudaGetSymbolAddress((void**)&w0h, g_wt0h);
    cudaGetSymbolAddress((void**)&w0l, g_wt0l);
    cudaGetSymbolAddress((void**)&w1h, g_wt1h);
    cudaGetSymbolAddress((void**)&w1l, g_wt1l);
    cudaGetSymbolAddress((void**)&w2h, g_wt2h);
    cudaGetSymbolAddress((void**)&w2l, g_wt2l);

    // prep: transpose + split weights (small, off critical path)
    {
        dim3 thr(32, 8);
        transpose_split_kernel<<<dim3(HDIM / 32, KFULL / 32), thr>>>(W0, KFULL, HDIM, w0h, w0l);
        transpose_split_kernel<<<dim3(HDIM / 32, HDIM / 32), thr>>>(W1, HDIM, HDIM, w1h, w1l);
        transpose_split_kernel<<<dim3(HDIM / 32, HDIM / 32), thr>>>(W2, HDIM, HDIM, w2h, w2l);
    }

    const dim3 grid(HDIM / BN, NAVAIL / BM);   // (8, 256)
    const float* W0tail = W0 + (size_t)KFULL * HDIM;   // rows 2048, 2049

    gemm_mma_kernel<KFULL, true><<<grid, NTHREADS, SMEM_BYTES>>>(
        x_m, x_op, w0h, w0l, b0, W0tail, job_srpt, pt, m_ids, op_idx, job_ids, h0);
    gemm_mma_kernel<HDIM, false><<<grid, NTHREADS, SMEM_BYTES>>>(
        h0, nullptr, w1h, w1l, b1, nullptr, nullptr, nullptr, nullptr, nullptr, nullptr, h1);
    gemm_mma_kernel<HDIM, false><<<grid, NTHREADS, SMEM_BYTES>>>(
        h1, nullptr, w2h, w2l, b2, nullptr, nullptr, nullptr, nullptr, nullptr, nullptr, h0);

    gemv_kernel<<<NAVAIL / 8, 256>>>(h0, W3, b3, sc);
    softmax_kernel<<<1, 1024>>>(sc, out, out_size);
}

// round 6
// speedup vs baseline: 2.5206x; 1.2058x over previous
#include <cuda_runtime.h>
#include <cuda_bf16.h>
#include <cstdint>
#include <math.h>

// ---------------------------------------------------------------------------
// Problem constants
// ---------------------------------------------------------------------------
#define HDIM   1024
#define NAVAIL 32768
#define KFULL  2048      // GEMM0 K (the +2 scalar features handled in epilogue)

// GEMM tiling (mma.sync m16n8k16 bf16)
#define BM 128
#define BN 128
#define BK 16
#define NTHREADS 256     // 8 warps: 4 (M) x 2 (N)

// Packed tile format: 128 rows x 16 bf16 = 4096 B. Row stride 32 B, XOR swizzle:
//   byte(r, ch, c) = r*32 + ((ch ^ ((r>>2)&1))<<4) + c*2   (ch = 8-col chunk)
// ldmatrix bank walk over 8 rows: 0,8,16,24,4,12,20,28 -> conflict-free.
#define ST_AH 0
#define ST_AL 4096
#define ST_BH 8192
#define ST_BL 12288
#define ST_STRIDE 16384
#define SMEM_BYTES (3 * ST_STRIDE)        // 49152 = default cap, no opt-in

// ---------------------------------------------------------------------------
// Device scratch (no runtime allocation allowed)
// ---------------------------------------------------------------------------
__device__ float g_h2[(size_t)NAVAIL * HDIM];                 // layer2 out (fp32)
__device__ float g_scores[NAVAIL];
__device__ __nv_bfloat16 g_a0h[(size_t)NAVAIL * HDIM];        // layer0 out hi (packed)
__device__ __nv_bfloat16 g_a0l[(size_t)NAVAIL * HDIM];        // layer0 out lo
__device__ __nv_bfloat16 g_a1h[(size_t)NAVAIL * HDIM];        // layer1 out hi
__device__ __nv_bfloat16 g_a1l[(size_t)NAVAIL * HDIM];        // layer1 out lo
__device__ __nv_bfloat16 g_wt0h[(size_t)HDIM * KFULL];        // W^T packed tiles
__device__ __nv_bfloat16 g_wt0l[(size_t)HDIM * KFULL];
__device__ __nv_bfloat16 g_wt1h[(size_t)HDIM * HDIM];
__device__ __nv_bfloat16 g_wt1l[(size_t)HDIM * HDIM];
__device__ __nv_bfloat16 g_wt2h[(size_t)HDIM * HDIM];
__device__ __nv_bfloat16 g_wt2l[(size_t)HDIM * HDIM];

// ---------------------------------------------------------------------------
// Helpers (all sm_80-era PTX; nothing arch-accelerated)
// ---------------------------------------------------------------------------
__device__ __forceinline__ uint32_t smem_u32(const void* p) {
    uint32_t a;
    asm("{ .reg .u64 t; cvta.to.shared.u64 t, %1; cvt.u32.u64 %0, t; }"
        : "=r"(a) : "l"(p));
    return a;
}
__device__ __forceinline__ void ldmx4(uint32_t* r, uint32_t addr) {
    asm volatile("ldmatrix.sync.aligned.m8n8.x4.shared.b16 {%0,%1,%2,%3}, [%4];"
                 : "=r"(r[0]), "=r"(r[1]), "=r"(r[2]), "=r"(r[3]) : "r"(addr));
}
__device__ __forceinline__ void mma_bf16(float* d, const uint32_t* a,
                                         uint32_t b0, uint32_t b1) {
    asm volatile("mma.sync.aligned.m16n8k16.row.col.f32.bf16.bf16.f32 "
                 "{%0,%1,%2,%3}, {%4,%5,%6,%7}, {%8,%9}, {%0,%1,%2,%3};"
                 : "+f"(d[0]), "+f"(d[1]), "+f"(d[2]), "+f"(d[3])
                 : "r"(a[0]), "r"(a[1]), "r"(a[2]), "r"(a[3]), "r"(b0), "r"(b1));
}
__device__ __forceinline__ void cp16(uint32_t dst, const void* src) {
    asm volatile("cp.async.cg.shared.global [%0], [%1], 16;"
                 :: "r"(dst), "l"(src) : "memory");
}
#define CP_COMMIT() asm volatile("cp.async.commit_group;" ::: "memory")
#define CP_WAIT1()  asm volatile("cp.async.wait_group 1;" ::: "memory")

__device__ __forceinline__ void split2(float a, float b, uint32_t& hi, uint32_t& lo) {
    __nv_bfloat16 ha = __float2bfloat16_rn(a);
    __nv_bfloat16 hb = __float2bfloat16_rn(b);
    __nv_bfloat16 la = __float2bfloat16_rn(a - __bfloat162float(ha));
    __nv_bfloat16 lb = __float2bfloat16_rn(b - __bfloat162float(hb));
    __nv_bfloat162 H; H.x = ha; H.y = hb;
    __nv_bfloat162 L; L.x = la; L.y = lb;
    hi = *reinterpret_cast<uint32_t*>(&H);
    lo = *reinterpret_cast<uint32_t*>(&L);
}

// ---------------------------------------------------------------------------
// Prep: transpose + bf16 hi/lo split of [K x N] fp32 weight into PACKED tiles:
// block (ntile, ktile) of 4096 B at ((n>>7)*(K/16) + (k>>4))*4096, swizzled.
// ---------------------------------------------------------------------------
__global__ void transpose_split_pack(const float* __restrict__ W, int K, int N,
                                     __nv_bfloat16* __restrict__ Th,
                                     __nv_bfloat16* __restrict__ Tl) {
    __shared__ float tbuf[32][33];
    const int nb = blockIdx.x * 32, kb = blockIdx.y * 32;
    const int tx = threadIdx.x, ty = threadIdx.y;   // (32, 8)
    #pragma unroll
    for (int j = 0; j < 32; j += 8)
        tbuf[ty + j][tx] = W[(size_t)(kb + ty + j) * N + nb + tx];
    __syncthreads();
    #pragma unroll
    for (int j = 0; j < 32; j += 8) {
        const float x = tbuf[tx][ty + j];            // = W[kb+tx][nb+ty+j]
        const int k = kb + tx;
        const int n = nb + ty + j;
        const __nv_bfloat16 h = __float2bfloat16_rn(x);
        const __nv_bfloat16 l = __float2bfloat16_rn(x - __bfloat162float(h));
        const int lr = n & 127, kc = k & 15, ch = kc >> 3;
        const size_t off = ((size_t)(n >> 7) * (K / 16) + (k >> 4)) * 4096
                         + lr * 32 + ((ch ^ ((lr >> 2) & 1)) << 4) + (kc & 7) * 2;
        *(__nv_bfloat16*)((char*)Th + off) = h;
        *(__nv_bfloat16*)((char*)Tl + off) = l;
    }
}

// ---------------------------------------------------------------------------
// Split-bf16 GEMM layer, 3-stage cp.async pipeline.
//   GATHER: A = gathered fp32 (x_m/x_op rows), split inline, STS path.
//   else:   A = packed bf16 hi/lo tiles, pure cp.async.
//   OUTPK:  write output as packed bf16 hi/lo tiles (for the next layer);
//   else:   write fp32 rows (for gemv).
// ---------------------------------------------------------------------------
template <int KTOT, bool GATHER, bool OUTPK>
__global__ __launch_bounds__(NTHREADS)
void gemm_mma_kernel(const void* __restrict__ Aa, const void* __restrict__ Ab,
                     const __nv_bfloat16* __restrict__ WTh,
                     const __nv_bfloat16* __restrict__ WTl,
                     const float* __restrict__ bias,
                     const float* __restrict__ W0tail,
                     const float* __restrict__ job_srpt,
                     const float* __restrict__ pt,
                     const int* __restrict__ m_ids,
                     const int* __restrict__ op_idx,
                     const int* __restrict__ job_ids,
                     void* __restrict__ outH, void* __restrict__ outL) {
    extern __shared__ char sm[];
    const uint32_t sbase = smem_u32(sm);
    const int tid = threadIdx.x, wid = tid >> 5, lane = tid & 31;
    const int wm = wid >> 1, wn = wid & 1;
    const int n0 = blockIdx.x * BN, m0 = blockIdx.y * BM;
    constexpr int T = KTOT / BK;

    // cp.async sources: packed blocks, advance by 4096 B per k-tile
    const char* srcBh = (const char*)WTh + (size_t)(n0 >> 7) * T * 4096 + tid * 16;
    const char* srcBl = (const char*)WTl + (size_t)(n0 >> 7) * T * 4096 + tid * 16;
    const char* srcAh = nullptr;
    const char* srcAl = nullptr;
    const float *pa0 = nullptr, *pb0 = nullptr, *pa1 = nullptr, *pb1 = nullptr;
    const int gr0 = tid >> 2, gc4 = tid & 3;          // gather mapping
    if constexpr (GATHER) {
        pa0 = (const float*)Aa + (size_t)m_ids[m0 + gr0] * HDIM;
        pb0 = (const float*)Ab + (size_t)op_idx[m0 + gr0] * HDIM;
        pa1 = (const float*)Aa + (size_t)m_ids[m0 + gr0 + 64] * HDIM;
        pb1 = (const float*)Ab + (size_t)op_idx[m0 + gr0 + 64] * HDIM;
    } else {
        srcAh = (const char*)Aa + (size_t)(m0 >> 7) * T * 4096 + tid * 16;
        srcAl = (const char*)Ab + (size_t)(m0 >> 7) * T * 4096 + tid * 16;
    }

    float acc[2][8][4];
    #pragma unroll
    for (int i = 0; i < 2; ++i)
        #pragma unroll
        for (int j = 0; j < 8; ++j)
            #pragma unroll
            for (int r = 0; r < 4; ++r) acc[i][j][r] = 0.f;

    auto ldgA = [&](int t, float4* aR) {
        const int kb = t * BK;
        const float* s0;
        const float* s1;
        if (kb < HDIM) { s0 = pa0 + kb; s1 = pa1 + kb; }
        else           { s0 = pb0 + (kb - HDIM); s1 = pb1 + (kb - HDIM); }
        aR[0] = *(const float4*)(s0 + gc4 * 4);
        aR[1] = *(const float4*)(s1 + gc4 * 4);
    };
    const int sch = gc4 >> 1, shalf = (gc4 & 1) * 8;
    const int sbit = (gr0 >> 2) & 1;                  // same for gr0 and gr0+64
    auto stsA = [&](int slot, const float4* aR) {
        char* bb = sm + slot * ST_STRIDE;
        #pragma unroll
        for (int i = 0; i < 2; ++i) {
            const int r = gr0 + i * 64;
            uint32_t h01, l01, h23, l23;
            split2(aR[i].x, aR[i].y, h01, l01);
            split2(aR[i].z, aR[i].w, h23, l23);
            const uint32_t off = r * 32 + ((sch ^ sbit) << 4) + shalf;
            *(uint2*)(bb + ST_AH + off) = make_uint2(h01, h23);
            *(uint2*)(bb + ST_AL + off) = make_uint2(l01, l23);
        }
    };
    auto cpStage = [&](int t, int slot) {
        const uint32_t d = sbase + slot * ST_STRIDE + tid * 16;
        const size_t o = (size_t)t * 4096;
        cp16(d + ST_BH, srcBh + o);
        cp16(d + ST_BL, srcBl + o);
        if constexpr (!GATHER) {
            cp16(d + ST_AH, srcAh + o);
            cp16(d + ST_AL, srcAl + o);
        }
    };

    // ---- prologue: stages 0, 1 ----
    float4 aRn[2];
    if constexpr (GATHER) {
        float4 aR0[2];
        ldgA(0, aR0);
        stsA(0, aR0);
        ldgA(1, aRn);
    }
    cpStage(0, 0); CP_COMMIT();
    cpStage(1, 1); CP_COMMIT();

    // per-lane ldmatrix offset (row + swizzled k-chunk)
    const uint32_t lofs = (lane & 15) * 32 + (((lane >> 4) ^ ((lane >> 2) & 1)) << 4);

    for (int t = 0; t < T; ++t) {
        CP_WAIT1();                 // stage t complete (last group may pend)
        __syncthreads();            // everyone done computing stage t-1
        if constexpr (GATHER) {
            if (t + 1 < T) stsA((t + 1) % 3, aRn);   // stage t+1 A (slot freed at t-2)
        }
        if (t + 2 < T) {
            if constexpr (GATHER) ldgA(t + 2, aRn);
            cpStage(t + 2, (t + 2) % 3);             // slot (t-1)%3, readers passed sync
        }
        CP_COMMIT();                // unconditional: keeps wait_group(1) semantics

        const uint32_t st = sbase + (t % 3) * ST_STRIDE;
        uint32_t ah[2][4], al[2][4], bh[4][4], bl[4][4];
        #pragma unroll
        for (int mt = 0; mt < 2; ++mt) {
            const uint32_t ra = st + ST_AH + wm * 1024 + mt * 512 + lofs;
            ldmx4(ah[mt], ra);
            ldmx4(al[mt], ra + (ST_AL - ST_AH));
        }
        #pragma unroll
        for (int p = 0; p < 4; ++p) {
            const uint32_t rb = st + ST_BH + wn * 2048 + p * 512 + lofs;
            ldmx4(bh[p], rb);
            ldmx4(bl[p], rb + (ST_BL - ST_BH));
        }
        #pragma unroll
        for (int mt = 0; mt < 2; ++mt)
            #pragma unroll
            for (int nt = 0; nt < 8; ++nt) {
                const int p = nt >> 1, o = nt & 1;
                mma_bf16(acc[mt][nt], ah[mt], bh[p][o], bh[p][2 + o]);
                mma_bf16(acc[mt][nt], ah[mt], bl[p][o], bl[p][2 + o]);
                mma_bf16(acc[mt][nt], al[mt], bh[p][o], bh[p][2 + o]);
            }
    }

    // ---- epilogue ----
    const int gq = lane >> 2, tg = lane & 3;
    #pragma unroll
    for (int mt = 0; mt < 2; ++mt) {
        const int lr0 = wm * 32 + mt * 16 + gq;       // local row in [0,128)
        const int lr1 = lr0 + 8;
        const int er0 = m0 + lr0, er1 = m0 + lr1;
        float js0 = 0.f, pv0 = 0.f, js1 = 0.f, pv1 = 0.f;
        if constexpr (GATHER) {
            js0 = job_srpt[job_ids[er0]]; pv0 = pt[er0];
            js1 = job_srpt[job_ids[er1]]; pv1 = pt[er1];
        }
        #pragma unroll
        for (int nt = 0; nt < 8; ++nt) {
            const int nc = n0 + wn * 64 + nt * 8 + tg * 2;
            const float bz0 = bias[nc], bz1 = bias[nc + 1];
            float e00 = 0.f, e01 = 0.f, e10 = 0.f, e11 = 0.f;
            if constexpr (GATHER) {
                const float wa0 = W0tail[nc], wa1 = W0tail[nc + 1];
                const float wb0 = W0tail[HDIM + nc], wb1 = W0tail[HDIM + nc + 1];
                e00 = js0 * wa0 + pv0 * wb0; e01 = js0 * wa1 + pv0 * wb1;
                e10 = js1 * wa0 + pv1 * wb0; e11 = js1 * wa1 + pv1 * wb1;
            }
            float v00 = acc[mt][nt][0] + bz0 + e00;
            float v01 = acc[mt][nt][1] + bz1 + e01;
            float v10 = acc[mt][nt][2] + bz0 + e10;
            float v11 = acc[mt][nt][3] + bz1 + e11;
            v00 = v00 > 0.f ? v00 : 0.01f * v00;
            v01 = v01 > 0.f ? v01 : 0.01f * v01;
            v10 = v10 > 0.f ? v10 : 0.01f * v10;
            v11 = v11 > 0.f ? v11 : 0.01f * v11;
            if constexpr (OUTPK) {
                // write packed hi/lo tiles for the next layer (its K = HDIM)
                const size_t blk = ((size_t)blockIdx.y * (HDIM / 16) + (nc >> 4)) * 4096;
                const uint32_t sw = ((((nc >> 3) & 1) ^ ((lr0 >> 2) & 1)) << 4);
                const uint32_t o0 = lr0 * 32 + sw + (nc & 7) * 2;   // lr1 has same sw bit
                const uint32_t o1 = lr1 * 32 + sw + (nc & 7) * 2;
                uint32_t h0, l0, h1, l1;
                split2(v00, v01, h0, l0);
                split2(v10, v11, h1, l1);
                *(uint32_t*)((char*)outH + blk + o0) = h0;
                *(uint32_t*)((char*)outL + blk + o0) = l0;
                *(uint32_t*)((char*)outH + blk + o1) = h1;
                *(uint32_t*)((char*)outL + blk + o1) = l1;
            } else {
                float* out = (float*)outH;
                *(float2*)(out + (size_t)er0 * HDIM + nc) = make_float2(v00, v01);
                *(float2*)(out + (size_t)er1 * HDIM + nc) = make_float2(v10, v11);
            }
        }
    }
}

// ---------------------------------------------------------------------------
// Final layer GEMV: scores[m] = h[m,:] . W3 + b3
// ---------------------------------------------------------------------------
__global__ void gemv_kernel(const float* __restrict__ hbuf,
                            const float* __restrict__ W3,
                            const float* __restrict__ b3,
                            float* __restrict__ scores) {
    const int gw = (int)((blockIdx.x * blockDim.x + threadIdx.x) >> 5);
    const int lane = threadIdx.x & 31;
    if (gw >= NAVAIL) return;
    const float4* hr = (const float4*)(hbuf + (size_t)gw * HDIM);
    const float4* wr = (const float4*)W3;
    float s = 0.f;
    #pragma unroll 4
    for (int i = lane; i < HDIM / 4; i += 32) {
        const float4 a = hr[i];
        const float4 w = wr[i];
        s += a.x * w.x + a.y * w.y + a.z * w.z + a.w * w.w;
    }
    #pragma unroll
    for (int off = 16; off > 0; off >>= 1)
        s += __shfl_down_sync(0xffffffffu, s, off);
    if (lane == 0) scores[gw] = s + b3[0];
}

// ---------------------------------------------------------------------------
// Softmax + argmax (first-max semantics), single block.
// ---------------------------------------------------------------------------
__global__ void softmax_kernel(const float* __restrict__ scores,
                               float* __restrict__ out, int out_size) {
    const int tid = threadIdx.x;
    const int lane = tid & 31;
    const int wid = tid >> 5;
    __shared__ float red_f[32];
    __shared__ int   red_i[32];
    __shared__ float red_s[32];

    float bmax = -INFINITY;
    int bidx = 0x7fffffff;
    for (int i = tid; i < NAVAIL; i += 1024) {
        const float v = scores[i];
        if (v > bmax) { bmax = v; bidx = i; }
    }
    #pragma unroll
    for (int off = 16; off > 0; off >>= 1) {
        const float om = __shfl_down_sync(0xffffffffu, bmax, off);
        const int oi = __shfl_down_sync(0xffffffffu, bidx, off);
        if (om > bmax || (om == bmax && oi < bidx)) { bmax = om; bidx = oi; }
    }
    if (lane == 0) { red_f[wid] = bmax; red_i[wid] = bidx; }
    __syncthreads();
    if (tid < 32) {
        bmax = red_f[tid];
        bidx = red_i[tid];
        #pragma unroll
        for (int off = 16; off > 0; off >>= 1) {
            const float om = __shfl_down_sync(0xffffffffu, bmax, off);
            const int oi = __shfl_down_sync(0xffffffffu, bidx, off);
            if (om > bmax || (om == bmax && oi < bidx)) { bmax = om; bidx = oi; }
        }
        if (tid == 0) { red_f[0] = bmax; red_i[0] = bidx; }
    }
    __syncthreads();
    const float gmax = red_f[0];
    const int gidx = red_i[0];

    float s = 0.f;
    for (int i = tid; i < NAVAIL; i += 1024) {
        const float e = expf(scores[i] - gmax);
        out[i] = e;
        s += e;
    }
    #pragma unroll
    for (int off = 16; off > 0; off >>= 1)
        s += __shfl_down_sync(0xffffffffu, s, off);
    if (lane == 0) red_s[wid] = s;
    __syncthreads();
    if (tid < 32) {
        s = red_s[tid];
        #pragma unroll
        for (int off = 16; off > 0; off >>= 1)
            s += __shfl_down_sync(0xffffffffu, s, off);
        if (tid == 0) red_s[0] = s;
    }
    __syncthreads();
    const float inv = 1.0f / red_s[0];
    for (int i = tid; i < NAVAIL; i += 1024)
        out[i] *= inv;
    for (int i = NAVAIL + tid; i < out_size; i += 1024)
        out[i] = (float)gidx;
}

// ---------------------------------------------------------------------------
// Launch. inputs: x_m, x_op, job_srpt, pt, W0, b0, W1, b1, W2, b2, W3, b3,
//                 m_ids, op_idx, job_ids
// Host API surface: cudaGetSymbolAddress + launches only (R5-proven minimum).
// ---------------------------------------------------------------------------
extern "C" void kernel_launch(void* const* d_in, const int* in_sizes, int n_in,
                              void* d_out, int out_size) {
    const float* x_m      = (const float*)d_in[0];
    const float* x_op     = (const float*)d_in[1];
    const float* job_srpt = (const float*)d_in[2];
    const float* pt       = (const float*)d_in[3];
    const float* W0       = (const float*)d_in[4];
    const float* b0       = (const float*)d_in[5];
    const float* W1       = (const float*)d_in[6];
    const float* b1       = (const float*)d_in[7];
    const float* W2       = (const float*)d_in[8];
    const float* b2       = (const float*)d_in[9];
    const float* W3       = (const float*)d_in[10];
    const float* b3       = (const float*)d_in[11];
    const int*   m_ids    = (const int*)d_in[12];
    const int*   op_idx   = (const int*)d_in[13];
    const int*   job_ids  = (const int*)d_in[14];
    float* out = (float*)d_out;

    float *h2, *sc;
    __nv_bfloat16 *a0h, *a0l, *a1h, *a1l;
    __nv_bfloat16 *w0h, *w0l, *w1h, *w1l, *w2h, *w2l;
    cudaGetSymbolAddress((void**)&h2, g_h2);
    cudaGetSymbolAddress((void**)&sc, g_scores);
    cudaGetSymbolAddress((void**)&a0h, g_a0h);
    cudaGetSymbolAddress((void**)&a0l, g_a0l);
    cudaGetSymbolAddress((void**)&a1h, g_a1h);
    cudaGetSymbolAddress((void**)&a1l, g_a1l);
    cudaGetSymbolAddress((void**)&w0h, g_wt0h);
    cudaGetSymbolAddress((void**)&w0l, g_wt0l);
    cudaGetSymbolAddress((void**)&w1h, g_wt1h);
    cudaGetSymbolAddress((void**)&w1l, g_wt1l);
    cudaGetSymbolAddress((void**)&w2h, g_wt2h);
    cudaGetSymbolAddress((void**)&w2l, g_wt2l);

    // prep: transpose + split + pack weights (small, off critical path)
    {
        dim3 thr(32, 8);
        transpose_split_pack<<<dim3(HDIM / 32, KFULL / 32), thr>>>(W0, KFULL, HDIM, w0h, w0l);
        transpose_split_pack<<<dim3(HDIM / 32, HDIM / 32), thr>>>(W1, HDIM, HDIM, w1h, w1l);
        transpose_split_pack<<<dim3(HDIM / 32, HDIM / 32), thr>>>(W2, HDIM, HDIM, w2h, w2l);
    }

    const dim3 grid(HDIM / BN, NAVAIL / BM);   // (8, 256)
    const float* W0tail = W0 + (size_t)KFULL * HDIM;   // rows 2048, 2049

    gemm_mma_kernel<KFULL, true, true><<<grid, NTHREADS, SMEM_BYTES>>>(
        x_m, x_op, w0h, w0l, b0, W0tail, job_srpt, pt, m_ids, op_idx, job_ids,
        a0h, a0l);
    gemm_mma_kernel<HDIM, false, true><<<grid, NTHREADS, SMEM_BYTES>>>(
        a0h, a0l, w1h, w1l, b1, nullptr, nullptr, nullptr, nullptr, nullptr, nullptr,
        a1h, a1l);
    gemm_mma_kernel<HDIM, false, false><<<grid, NTHREADS, SMEM_BYTES>>>(
        a1h, a1l, w2h, w2l, b2, nullptr, nullptr, nullptr, nullptr, nullptr, nullptr,
        h2, nullptr);

    gemv_kernel<<<NAVAIL / 8, 256>>>(h2, W3, b3, sc);
    softmax_kernel<<<1, 1024>>>(sc, out, out_size);
}